// round 12
// baseline (speedup 1.0000x reference)
#include <cuda_runtime.h>
#include <cuda_bf16.h>
#include <stdint.h>

#define S_REAL   308
#define SP       320     // padded state count
#define E_DIM    126
#define T_LEN    4096
#define NBATCH   32
#define NIP      160     // SP/2 pair-words of alpha
#define SCAN_THREADS 512

// Scratch (device globals — no allocation in kernel_launch)
__device__ __nv_bfloat16 g_emis[(size_t)NBATCH * T_LEN * SP];   // 80 MB
// A pair-words for the 512-thread scan. Tile (ig, jj) owns i-pairs
// ip = ig*20 + ql*4 + s (ql=0..4, s=0..3) for columns j = jj + 64*c (c=0..4).
// uint4 (ql,c) lives at uint4 index ((ig*5+ql)*5 + c)*64 + jj. Prescaled x128.
__device__ uint32_t g_a[8 * 5 * 5 * 64 * 4];                     // 200 KB

__device__ __forceinline__ __nv_bfloat162 u32_bf2(uint32_t v) {
    return *reinterpret_cast<__nv_bfloat162*>(&v);
}
__device__ __forceinline__ uint32_t bf2_u32(__nv_bfloat162 v) {
    return *reinterpret_cast<uint32_t*>(&v);
}

// ---------------------------------------------------------------------------
// Merged prep + emission GEMM. Blocks (bx==0, by<80) pack A*128 into g_a,
// then all blocks run the emission GEMM tile. 2 launches per call total.
// ---------------------------------------------------------------------------
__global__ void __launch_bounds__(256)
prep_gemm_kernel(const float* __restrict__ inp, const float* __restrict__ Bm,
                 const float* __restrict__ A) {
    const int tid = threadIdx.x;

    if (blockIdx.x == 0 && blockIdx.y < 80) {
        int gt = blockIdx.y * 256 + tid;
        for (int wi = gt; wi < 160 * SP; wi += 80 * 256) {
            int ip = wi / SP;
            int j  = wi - ip * SP;
            int i0 = 2 * ip, i1 = i0 + 1;
            float a0 = (i0 < S_REAL && j < S_REAL) ? A[i0 * S_REAL + j] * 128.f : 0.f;
            float a1 = (i1 < S_REAL && j < S_REAL) ? A[i1 * S_REAL + j] * 128.f : 0.f;
            uint32_t word = bf2_u32(__floats2bfloat162_rn(a0, a1));
            int ig = ip / 20, r = ip % 20, ql = r >> 2, s = r & 3;
            int c = j >> 6, jj = j & 63;
            g_a[((((ig * 5 + ql) * 5 + c) * 64) + jj) * 4 + s] = word;
        }
    }

    // ---------------- GEMM part (all blocks) ----------------
    __shared__ uint32_t sAp[64][16];
    __shared__ uint32_t sBp[16][64];

    const int tx = tid & 15;
    const int ty = tid >> 4;
    const int n0 = blockIdx.x * 64;
    const int m0 = blockIdx.y * 64;

    float acc[4][4];
#pragma unroll
    for (int u = 0; u < 4; ++u)
#pragma unroll
        for (int v = 0; v < 4; ++v) acc[u][v] = 0.f;

    const __nv_bfloat162 zero2 = __floats2bfloat162_rn(0.f, 0.f);

    for (int k0 = 0; k0 < 128; k0 += 32) {
#pragma unroll
        for (int r = 0; r < 4; ++r) {
            int lin = tid + r * 256;
            int mm = lin >> 4, kp = lin & 15;
            int k = k0 + 2 * kp;
            __nv_bfloat162 w = zero2;
            if (k < E_DIM) {
                float2 f = *reinterpret_cast<const float2*>(
                    &inp[(size_t)(m0 + mm) * E_DIM + k]);
                w = __floats2bfloat162_rn(f.x, f.y);
            }
            sAp[mm][kp] = bf2_u32(w);
        }
#pragma unroll
        for (int r = 0; r < 4; ++r) {
            int lin = tid + r * 256;
            int kp = lin >> 6, n = lin & 63;
            int k = k0 + 2 * kp;
            int nn = n0 + n;
            __nv_bfloat162 w = zero2;
            if (k < E_DIM && nn < S_REAL) {
                float2 f = *reinterpret_cast<const float2*>(
                    &Bm[(size_t)nn * E_DIM + k]);
                w = __floats2bfloat162_rn(f.x, f.y);
            }
            sBp[kp][n] = bf2_u32(w);
        }
        __syncthreads();

        __nv_bfloat162 acc2[4][4];
#pragma unroll
        for (int u = 0; u < 4; ++u)
#pragma unroll
            for (int v = 0; v < 4; ++v) acc2[u][v] = zero2;

#pragma unroll
        for (int kp = 0; kp < 16; ++kp) {
            uint4 bv = *reinterpret_cast<const uint4*>(&sBp[kp][tx * 4]);
            uint32_t a0 = sAp[ty * 4 + 0][kp];
            uint32_t a1 = sAp[ty * 4 + 1][kp];
            uint32_t a2 = sAp[ty * 4 + 2][kp];
            uint32_t a3 = sAp[ty * 4 + 3][kp];
            __nv_bfloat162 b0 = u32_bf2(bv.x), b1 = u32_bf2(bv.y);
            __nv_bfloat162 b2 = u32_bf2(bv.z), b3 = u32_bf2(bv.w);
            acc2[0][0] = __hfma2(u32_bf2(a0), b0, acc2[0][0]);
            acc2[0][1] = __hfma2(u32_bf2(a0), b1, acc2[0][1]);
            acc2[0][2] = __hfma2(u32_bf2(a0), b2, acc2[0][2]);
            acc2[0][3] = __hfma2(u32_bf2(a0), b3, acc2[0][3]);
            acc2[1][0] = __hfma2(u32_bf2(a1), b0, acc2[1][0]);
            acc2[1][1] = __hfma2(u32_bf2(a1), b1, acc2[1][1]);
            acc2[1][2] = __hfma2(u32_bf2(a1), b2, acc2[1][2]);
            acc2[1][3] = __hfma2(u32_bf2(a1), b3, acc2[1][3]);
            acc2[2][0] = __hfma2(u32_bf2(a2), b0, acc2[2][0]);
            acc2[2][1] = __hfma2(u32_bf2(a2), b1, acc2[2][1]);
            acc2[2][2] = __hfma2(u32_bf2(a2), b2, acc2[2][2]);
            acc2[2][3] = __hfma2(u32_bf2(a2), b3, acc2[2][3]);
            acc2[3][0] = __hfma2(u32_bf2(a3), b0, acc2[3][0]);
            acc2[3][1] = __hfma2(u32_bf2(a3), b1, acc2[3][1]);
            acc2[3][2] = __hfma2(u32_bf2(a3), b2, acc2[3][2]);
            acc2[3][3] = __hfma2(u32_bf2(a3), b3, acc2[3][3]);
        }
#pragma unroll
        for (int u = 0; u < 4; ++u)
#pragma unroll
            for (int v = 0; v < 4; ++v) {
                float2 p = __bfloat1622float2(acc2[u][v]);
                acc[u][v] += p.x + p.y;
            }
        __syncthreads();
    }
#pragma unroll
    for (int u = 0; u < 4; ++u) {
        int m = m0 + ty * 4 + u;
        size_t base = (size_t)m * SP + n0 + tx * 4;
#pragma unroll
        for (int v = 0; v < 4; v += 2) {
            __nv_bfloat162 p = __floats2bfloat162_rn(acc[u][v], acc[u][v + 1]);
            *reinterpret_cast<uint32_t*>(&g_emis[base + v]) = bf2_u32(p);
        }
    }
}

// ---------------------------------------------------------------------------
// Scan: one CTA per batch, 512 threads (16 warps). Thread (ig = tid&7,
// jj = tid>>3) owns a 20-i-pair x 5-column tile of A, fully register-resident
// (25 uint4 = 100 regs). All 8 i-group partials for a j live in ONE warp
// (lanes +-1,2,4) -> reduce is 3 shfl_xor, no smem round-trip, ONE barrier
// per step. Emission loaded on ig==0 lanes at iteration start (latency hidden
// by the 800-cyc fma phase). A prescaled by 128; renorm + log every 16 steps;
// ll -= 4095*log(128).
// ---------------------------------------------------------------------------
__global__ void __launch_bounds__(SCAN_THREADS, 1)
scan_kernel(const float* __restrict__ Ivec, float* __restrict__ out) {
    __shared__ uint32_t s_alpha[2][NIP];   // bf16 alpha pairs, double-buffered
    __shared__ float    s_w[16];
    __shared__ float    s_inv;

    const int b    = blockIdx.x;
    const int tid  = threadIdx.x;
    const int ig   = tid & 7;              // i-pair group (within warp!)
    const int jj   = tid >> 3;             // 0..63
    const int wrp  = tid >> 5;
    const int lane = tid & 31;

    const __nv_bfloat16* erow = g_emis + (size_t)b * T_LEN * SP;
    const uint4* Aq = reinterpret_cast<const uint4*>(g_a);

    // whole A tile register-resident: rA[ql*5 + c], 25 uint4 = 100 regs
    uint4 rA[25];
#pragma unroll
    for (int ql = 0; ql < 5; ++ql)
#pragma unroll
        for (int c = 0; c < 5; ++c)
            rA[ql * 5 + c] = Aq[(((ig * 5 + ql) * 5 + c) * 64) + jj];

    // t = 0: alpha0 = I * e0 (unnormalized, NOT prescaled) into buffer 1
    if (tid < NIP) {
        int j0 = 2 * tid, j1 = j0 + 1;
        float e0 = __bfloat162float(erow[j0]);
        float e1 = __bfloat162float(erow[j1]);
        float w0 = (j0 < S_REAL) ? Ivec[j0] : 0.f;
        float w1 = (j1 < S_REAL) ? Ivec[j1] : 0.f;
        s_alpha[1][tid] = bf2_u32(__floats2bfloat162_rn(w0 * e0, w1 * e1));
    }
    __syncthreads();

    float ll = 0.f;
    const __nv_bfloat162 zero2 = __floats2bfloat162_rn(0.f, 0.f);
    const bool is_w = (ig == 0);

    for (int t = 1; t < T_LEN; ++t) {
        const int cur = t & 1;

        // emission for THIS step, ig==0 lanes only; consumed after the fma
        // phase (~800 cyc later), so DRAM latency is hidden.
        float e0c = 0.f, e1c = 0.f, e2c = 0.f, e3c = 0.f, e4c = 0.f;
        if (is_w) {
            const __nv_bfloat16* ep = erow + (size_t)t * SP + jj;
            e0c = __bfloat162float(ep[0]);
            e1c = __bfloat162float(ep[64]);
            e2c = __bfloat162float(ep[128]);
            e3c = __bfloat162float(ep[192]);
            e4c = __bfloat162float(ep[256]);
        }

        const uint4* al4 = reinterpret_cast<const uint4*>(s_alpha[cur]);

        __nv_bfloat162 a0 = zero2, a1 = zero2, a2 = zero2, a3 = zero2, a4 = zero2;

        // 5 broadcast alpha quads (8 distinct conflict-free addrs per warp)
#pragma unroll
        for (int ql = 0; ql < 5; ++ql) {
            uint4 av = al4[ig * 5 + ql];
            __nv_bfloat162 x0 = u32_bf2(av.x), x1 = u32_bf2(av.y);
            __nv_bfloat162 x2 = u32_bf2(av.z), x3 = u32_bf2(av.w);
            uint4 w;
            w = rA[ql * 5 + 0];
            a0 = __hfma2(u32_bf2(w.x), x0, a0); a0 = __hfma2(u32_bf2(w.y), x1, a0);
            a0 = __hfma2(u32_bf2(w.z), x2, a0); a0 = __hfma2(u32_bf2(w.w), x3, a0);
            w = rA[ql * 5 + 1];
            a1 = __hfma2(u32_bf2(w.x), x0, a1); a1 = __hfma2(u32_bf2(w.y), x1, a1);
            a1 = __hfma2(u32_bf2(w.z), x2, a1); a1 = __hfma2(u32_bf2(w.w), x3, a1);
            w = rA[ql * 5 + 2];
            a2 = __hfma2(u32_bf2(w.x), x0, a2); a2 = __hfma2(u32_bf2(w.y), x1, a2);
            a2 = __hfma2(u32_bf2(w.z), x2, a2); a2 = __hfma2(u32_bf2(w.w), x3, a2);
            w = rA[ql * 5 + 3];
            a3 = __hfma2(u32_bf2(w.x), x0, a3); a3 = __hfma2(u32_bf2(w.y), x1, a3);
            a3 = __hfma2(u32_bf2(w.z), x2, a3); a3 = __hfma2(u32_bf2(w.w), x3, a3);
            w = rA[ql * 5 + 4];
            a4 = __hfma2(u32_bf2(w.x), x0, a4); a4 = __hfma2(u32_bf2(w.y), x1, a4);
            a4 = __hfma2(u32_bf2(w.z), x2, a4); a4 = __hfma2(u32_bf2(w.w), x3, a4);
        }

        float2 p;
        p = __bfloat1622float2(a0); float o0 = p.x + p.y;
        p = __bfloat1622float2(a1); float o1 = p.x + p.y;
        p = __bfloat1622float2(a2); float o2 = p.x + p.y;
        p = __bfloat1622float2(a3); float o3 = p.x + p.y;
        p = __bfloat1622float2(a4); float o4 = p.x + p.y;

        // warp-local 8-way i-group reduce (lanes +-1, +-2, +-4 share jj)
#pragma unroll
        for (int off = 1; off <= 4; off <<= 1) {
            o0 += __shfl_xor_sync(0xffffffffu, o0, off);
            o1 += __shfl_xor_sync(0xffffffffu, o1, off);
            o2 += __shfl_xor_sync(0xffffffffu, o2, off);
            o3 += __shfl_xor_sync(0xffffffffu, o3, off);
            o4 += __shfl_xor_sync(0xffffffffu, o4, off);
        }

        // apply emission on ig==0 lanes (others carry garbage, masked below)
        o0 *= e0c; o1 *= e1c; o2 *= e2c; o3 *= e3c; o4 *= e4c;

        if ((t & 15) == 15) {
            // z = sum over all j: mask to ig==0, then full warp reduce
            float s = is_w ? (o0 + o1) + (o2 + o3) + o4 : 0.f;
#pragma unroll
            for (int off = 16; off > 0; off >>= 1)
                s += __shfl_xor_sync(0xffffffffu, s, off);
            if (lane == 0) s_w[wrp] = s;
            __syncthreads();
            if (tid == 0) {
                float z = 0.f;
#pragma unroll
                for (int k = 0; k < 16; ++k) z += s_w[k];
                ll += logf(z);
                s_inv = 1.0f / z;
            }
            __syncthreads();
            o0 *= s_inv; o1 *= s_inv; o2 *= s_inv; o3 *= s_inv; o4 *= s_inv;
        }

        // pack (jj, jj+1) pairs: partner is lane+8 (same ig, jj+1)
        float q0 = __shfl_down_sync(0xffffffffu, o0, 8);
        float q1 = __shfl_down_sync(0xffffffffu, o1, 8);
        float q2 = __shfl_down_sync(0xffffffffu, o2, 8);
        float q3 = __shfl_down_sync(0xffffffffu, o3, 8);
        float q4 = __shfl_down_sync(0xffffffffu, o4, 8);
        if (is_w && (jj & 1) == 0) {
            int wbase = jj >> 1;
            uint32_t* dst = s_alpha[cur ^ 1];
            dst[wbase      ] = bf2_u32(__floats2bfloat162_rn(o0, q0));
            dst[wbase + 32 ] = bf2_u32(__floats2bfloat162_rn(o1, q1));
            dst[wbase + 64 ] = bf2_u32(__floats2bfloat162_rn(o2, q2));
            dst[wbase + 96 ] = bf2_u32(__floats2bfloat162_rn(o3, q3));
            dst[wbase + 128] = bf2_u32(__floats2bfloat162_rn(o4, q4));
        }
        __syncthreads();
    }

    // each of the 4095 steps carried an extra factor 128 (folded into A)
    if (tid == 0) out[b] = ll - 4095.0f * logf(128.0f);
}

// ---------------------------------------------------------------------------
extern "C" void kernel_launch(void* const* d_in, const int* in_sizes, int n_in,
                              void* d_out, int out_size) {
    const float* inputs = nullptr;
    const float* A      = nullptr;
    const float* Bm     = nullptr;
    const float* Ivec   = nullptr;
    for (int i = 0; i < n_in; ++i) {
        switch (in_sizes[i]) {
            case NBATCH * T_LEN * E_DIM: inputs = (const float*)d_in[i]; break;
            case S_REAL * S_REAL:        A      = (const float*)d_in[i]; break;
            case S_REAL * E_DIM:         Bm     = (const float*)d_in[i]; break;
            case S_REAL:                 Ivec   = (const float*)d_in[i]; break;
            default: break;
        }
    }
    if (!inputs) inputs = (const float*)d_in[0];
    if (!A)      A      = (const float*)d_in[1];
    if (!Bm)     Bm     = (const float*)d_in[2];
    if (!Ivec)   Ivec   = (const float*)d_in[3];
    float* out = (float*)d_out;

    dim3 ggrid(SP / 64, (NBATCH * T_LEN) / 64);   // (5, 2048)
    prep_gemm_kernel<<<ggrid, 256>>>(inputs, Bm, A);

    scan_kernel<<<NBATCH, SCAN_THREADS>>>(Ivec, out);
    (void)out_size;
}

// round 13
// speedup vs baseline: 1.1672x; 1.1672x over previous
#include <cuda_runtime.h>
#include <cuda_bf16.h>
#include <stdint.h>

#define S_REAL   308
#define SP       320     // padded state count
#define E_DIM    126
#define T_LEN    4096
#define NBATCH   32
#define NIP      160     // SP/2 pair-words of alpha
#define SCAN_THREADS 512

// Scratch (device globals — no allocation in kernel_launch)
__device__ __nv_bfloat16 g_emis[(size_t)NBATCH * T_LEN * SP];   // 80 MB
// A pair-words for the 512-thread scan. Tile (ig, jj) owns i-pairs
// ip = ig*20 + ql*4 + s (ql=0..4, s=0..3) for columns j = jj + 64*c (c=0..4).
// uint4 (ql,c) lives at uint4 index ((ig*5+ql)*5 + c)*64 + jj. Prescaled x128.
__device__ uint32_t g_a[8 * 5 * 5 * 64 * 4];                     // 200 KB

__device__ __forceinline__ __nv_bfloat162 u32_bf2(uint32_t v) {
    return *reinterpret_cast<__nv_bfloat162*>(&v);
}
__device__ __forceinline__ uint32_t bf2_u32(__nv_bfloat162 v) {
    return *reinterpret_cast<uint32_t*>(&v);
}
// bf16x2 -> fp32 sum via ALU-pipe bit tricks (SHF/LOP), one FADD on fma pipe
__device__ __forceinline__ float bf2_sum(__nv_bfloat162 v) {
    uint32_t u = bf2_u32(v);
    return __uint_as_float(u << 16) + __uint_as_float(u & 0xffff0000u);
}

// ---------------------------------------------------------------------------
// Merged prep + emission GEMM. Blocks (bx==0, by<80) pack A*128 into g_a,
// then all blocks run the emission GEMM tile. 2 launches per call total.
// ---------------------------------------------------------------------------
__global__ void __launch_bounds__(256)
prep_gemm_kernel(const float* __restrict__ inp, const float* __restrict__ Bm,
                 const float* __restrict__ A) {
    const int tid = threadIdx.x;

    if (blockIdx.x == 0 && blockIdx.y < 80) {
        int gt = blockIdx.y * 256 + tid;
        for (int wi = gt; wi < 160 * SP; wi += 80 * 256) {
            int ip = wi / SP;
            int j  = wi - ip * SP;
            int i0 = 2 * ip, i1 = i0 + 1;
            float a0 = (i0 < S_REAL && j < S_REAL) ? A[i0 * S_REAL + j] * 128.f : 0.f;
            float a1 = (i1 < S_REAL && j < S_REAL) ? A[i1 * S_REAL + j] * 128.f : 0.f;
            uint32_t word = bf2_u32(__floats2bfloat162_rn(a0, a1));
            int ig = ip / 20, r = ip % 20, ql = r >> 2, s = r & 3;
            int c = j >> 6, jj = j & 63;
            g_a[((((ig * 5 + ql) * 5 + c) * 64) + jj) * 4 + s] = word;
        }
    }

    // ---------------- GEMM part (all blocks) ----------------
    __shared__ uint32_t sAp[64][16];
    __shared__ uint32_t sBp[16][64];

    const int tx = tid & 15;
    const int ty = tid >> 4;
    const int n0 = blockIdx.x * 64;
    const int m0 = blockIdx.y * 64;

    float acc[4][4];
#pragma unroll
    for (int u = 0; u < 4; ++u)
#pragma unroll
        for (int v = 0; v < 4; ++v) acc[u][v] = 0.f;

    const __nv_bfloat162 zero2 = __floats2bfloat162_rn(0.f, 0.f);

    for (int k0 = 0; k0 < 128; k0 += 32) {
#pragma unroll
        for (int r = 0; r < 4; ++r) {
            int lin = tid + r * 256;
            int mm = lin >> 4, kp = lin & 15;
            int k = k0 + 2 * kp;
            __nv_bfloat162 w = zero2;
            if (k < E_DIM) {
                float2 f = *reinterpret_cast<const float2*>(
                    &inp[(size_t)(m0 + mm) * E_DIM + k]);
                w = __floats2bfloat162_rn(f.x, f.y);
            }
            sAp[mm][kp] = bf2_u32(w);
        }
#pragma unroll
        for (int r = 0; r < 4; ++r) {
            int lin = tid + r * 256;
            int kp = lin >> 6, n = lin & 63;
            int k = k0 + 2 * kp;
            int nn = n0 + n;
            __nv_bfloat162 w = zero2;
            if (k < E_DIM && nn < S_REAL) {
                float2 f = *reinterpret_cast<const float2*>(
                    &Bm[(size_t)nn * E_DIM + k]);
                w = __floats2bfloat162_rn(f.x, f.y);
            }
            sBp[kp][n] = bf2_u32(w);
        }
        __syncthreads();

        __nv_bfloat162 acc2[4][4];
#pragma unroll
        for (int u = 0; u < 4; ++u)
#pragma unroll
            for (int v = 0; v < 4; ++v) acc2[u][v] = zero2;

#pragma unroll
        for (int kp = 0; kp < 16; ++kp) {
            uint4 bv = *reinterpret_cast<const uint4*>(&sBp[kp][tx * 4]);
            uint32_t a0 = sAp[ty * 4 + 0][kp];
            uint32_t a1 = sAp[ty * 4 + 1][kp];
            uint32_t a2 = sAp[ty * 4 + 2][kp];
            uint32_t a3 = sAp[ty * 4 + 3][kp];
            __nv_bfloat162 b0 = u32_bf2(bv.x), b1 = u32_bf2(bv.y);
            __nv_bfloat162 b2 = u32_bf2(bv.z), b3 = u32_bf2(bv.w);
            acc2[0][0] = __hfma2(u32_bf2(a0), b0, acc2[0][0]);
            acc2[0][1] = __hfma2(u32_bf2(a0), b1, acc2[0][1]);
            acc2[0][2] = __hfma2(u32_bf2(a0), b2, acc2[0][2]);
            acc2[0][3] = __hfma2(u32_bf2(a0), b3, acc2[0][3]);
            acc2[1][0] = __hfma2(u32_bf2(a1), b0, acc2[1][0]);
            acc2[1][1] = __hfma2(u32_bf2(a1), b1, acc2[1][1]);
            acc2[1][2] = __hfma2(u32_bf2(a1), b2, acc2[1][2]);
            acc2[1][3] = __hfma2(u32_bf2(a1), b3, acc2[1][3]);
            acc2[2][0] = __hfma2(u32_bf2(a2), b0, acc2[2][0]);
            acc2[2][1] = __hfma2(u32_bf2(a2), b1, acc2[2][1]);
            acc2[2][2] = __hfma2(u32_bf2(a2), b2, acc2[2][2]);
            acc2[2][3] = __hfma2(u32_bf2(a2), b3, acc2[2][3]);
            acc2[3][0] = __hfma2(u32_bf2(a3), b0, acc2[3][0]);
            acc2[3][1] = __hfma2(u32_bf2(a3), b1, acc2[3][1]);
            acc2[3][2] = __hfma2(u32_bf2(a3), b2, acc2[3][2]);
            acc2[3][3] = __hfma2(u32_bf2(a3), b3, acc2[3][3]);
        }
#pragma unroll
        for (int u = 0; u < 4; ++u)
#pragma unroll
            for (int v = 0; v < 4; ++v) {
                float2 p = __bfloat1622float2(acc2[u][v]);
                acc[u][v] += p.x + p.y;
            }
        __syncthreads();
    }
#pragma unroll
    for (int u = 0; u < 4; ++u) {
        int m = m0 + ty * 4 + u;
        size_t base = (size_t)m * SP + n0 + tx * 4;
#pragma unroll
        for (int v = 0; v < 4; v += 2) {
            __nv_bfloat162 p = __floats2bfloat162_rn(acc[u][v], acc[u][v + 1]);
            *reinterpret_cast<uint32_t*>(&g_emis[base + v]) = bf2_u32(p);
        }
    }
}

// ---------------------------------------------------------------------------
// Scan: one CTA per batch, 512 threads (16 warps). R11 skeleton: thread
// (ig = tid>>6, jj = tid&63) owns a 20-i-pair x 5-column A tile, fully
// register-resident (25 uint4 = 100 regs); warp-uniform alpha broadcasts;
// smem s_red 8-way reduce; 2 barriers/step. Changes vs R11:
//  - fma inner loop interleaves the 5 accumulators (no RAW chains)
//  - bf16x2 collapse via ALU-pipe bit tricks
//  - DEFERRED renorm: z partials between the existing barriers, tid0
//    finalizes s_inv after BAR2 (overlapped with next fma), scale applied
//    one step late. No extra barriers on renorm steps.
// A prescaled by 128; ll -= 4095*log(128).
// ---------------------------------------------------------------------------
__global__ void __launch_bounds__(SCAN_THREADS, 1)
scan_kernel(const float* __restrict__ Ivec, float* __restrict__ out) {
    __shared__ uint32_t s_alpha[2][NIP];   // bf16 alpha pairs, double-buffered
    __shared__ float    s_w[10];
    __shared__ float    s_red[8][SP];      // per-i-group partials
    __shared__ float    s_inv;

    const int b    = blockIdx.x;
    const int tid  = threadIdx.x;
    const int ig   = tid >> 6;             // 0..7  (i-pair group of 20)
    const int jj   = tid & 63;             // 0..63
    const int wrp  = tid >> 5;
    const int lane = tid & 31;

    const __nv_bfloat16* erow = g_emis + (size_t)b * T_LEN * SP;
    const uint4* Aq = reinterpret_cast<const uint4*>(g_a);

    // whole A tile register-resident: rA[ql*5 + c], 25 uint4 = 100 regs
    uint4 rA[25];
#pragma unroll
    for (int ql = 0; ql < 5; ++ql)
#pragma unroll
        for (int c = 0; c < 5; ++c)
            rA[ql * 5 + c] = Aq[(((ig * 5 + ql) * 5 + c) * 64) + jj];

    // t = 0: alpha0 = I * e0 (unnormalized, NOT prescaled) into buffer 1
    if (tid < NIP) {
        int j0 = 2 * tid, j1 = j0 + 1;
        float e0 = __bfloat162float(erow[j0]);
        float e1 = __bfloat162float(erow[j1]);
        float w0 = (j0 < S_REAL) ? Ivec[j0] : 0.f;
        float w1 = (j1 < S_REAL) ? Ivec[j1] : 0.f;
        s_alpha[1][tid] = bf2_u32(__floats2bfloat162_rn(w0 * e0, w1 * e1));
    }
    if (tid == 0) s_inv = 1.0f;
    __syncthreads();

    float ll = 0.f;
    float e_cur = 0.f;
    if (tid < SP) e_cur = __bfloat162float(erow[(size_t)SP + tid]);

    const __nv_bfloat162 zero2 = __floats2bfloat162_rn(0.f, 0.f);

    for (int t = 1; t < T_LEN; ++t) {
        const int cur = t & 1;
        float e_next = 0.f;
        if (t + 1 < T_LEN && tid < SP)
            e_next = __bfloat162float(erow[(size_t)(t + 1) * SP + tid]);

        const uint4* al4 = reinterpret_cast<const uint4*>(s_alpha[cur]);

        __nv_bfloat162 a0 = zero2, a1 = zero2, a2 = zero2, a3 = zero2, a4 = zero2;

        // 5 broadcast alpha quads; accumulators interleaved (s-outer, c-inner)
#pragma unroll
        for (int ql = 0; ql < 5; ++ql) {
            uint4 av = al4[ig * 5 + ql];
            uint4 w0 = rA[ql * 5 + 0], w1 = rA[ql * 5 + 1], w2 = rA[ql * 5 + 2];
            uint4 w3 = rA[ql * 5 + 3], w4 = rA[ql * 5 + 4];
            __nv_bfloat162 x;
            x = u32_bf2(av.x);
            a0 = __hfma2(u32_bf2(w0.x), x, a0);
            a1 = __hfma2(u32_bf2(w1.x), x, a1);
            a2 = __hfma2(u32_bf2(w2.x), x, a2);
            a3 = __hfma2(u32_bf2(w3.x), x, a3);
            a4 = __hfma2(u32_bf2(w4.x), x, a4);
            x = u32_bf2(av.y);
            a0 = __hfma2(u32_bf2(w0.y), x, a0);
            a1 = __hfma2(u32_bf2(w1.y), x, a1);
            a2 = __hfma2(u32_bf2(w2.y), x, a2);
            a3 = __hfma2(u32_bf2(w3.y), x, a3);
            a4 = __hfma2(u32_bf2(w4.y), x, a4);
            x = u32_bf2(av.z);
            a0 = __hfma2(u32_bf2(w0.z), x, a0);
            a1 = __hfma2(u32_bf2(w1.z), x, a1);
            a2 = __hfma2(u32_bf2(w2.z), x, a2);
            a3 = __hfma2(u32_bf2(w3.z), x, a3);
            a4 = __hfma2(u32_bf2(w4.z), x, a4);
            x = u32_bf2(av.w);
            a0 = __hfma2(u32_bf2(w0.w), x, a0);
            a1 = __hfma2(u32_bf2(w1.w), x, a1);
            a2 = __hfma2(u32_bf2(w2.w), x, a2);
            a3 = __hfma2(u32_bf2(w3.w), x, a3);
            a4 = __hfma2(u32_bf2(w4.w), x, a4);
        }

        // collapse via ALU-pipe bit tricks, store per-i-group partials
        s_red[ig][jj      ] = bf2_sum(a0);
        s_red[ig][jj + 64 ] = bf2_sum(a1);
        s_red[ig][jj + 128] = bf2_sum(a2);
        s_red[ig][jj + 192] = bf2_sum(a3);
        s_red[ig][jj + 256] = bf2_sum(a4);
        __syncthreads();                         // BAR1

        float o = 0.f;
        if (tid < SP) {
            o = ((s_red[0][tid] + s_red[1][tid]) + (s_red[2][tid] + s_red[3][tid]))
              + ((s_red[4][tid] + s_red[5][tid]) + (s_red[6][tid] + s_red[7][tid]));
            o *= e_cur;
            if ((t & 15) == 0) o *= s_inv;       // deferred scale from t-1
        }

        if ((t & 15) == 15) {
            // z warp-partials (warps 0..9 hold all 320 j's)
            if (wrp < 10) {
                float s = o;
#pragma unroll
                for (int off = 16; off > 0; off >>= 1)
                    s += __shfl_xor_sync(0xffffffffu, s, off);
                if (lane == 0) s_w[wrp] = s;
            }
        }

        // pack (j even, j odd) lane pair; even lane stores the word
        if (tid < SP) {
            float op = __shfl_down_sync(0xffffffffu, o, 1);
            if ((lane & 1) == 0)
                s_alpha[cur ^ 1][tid >> 1] =
                    bf2_u32(__floats2bfloat162_rn(o, op));
        }
        __syncthreads();                         // BAR2

        if ((t & 15) == 15 && tid == 0) {
            // overlapped with the next step's fma phase; readers consume
            // s_inv only after the next BAR1.
            float z = 0.f;
#pragma unroll
            for (int k = 0; k < 10; ++k) z += s_w[k];
            ll += logf(z);
            s_inv = 1.0f / z;
        }

        e_cur = e_next;
    }

    // each of the 4095 steps carried an extra factor 128 (folded into A);
    // last renorm lands exactly on t=4095, so ll is complete.
    if (tid == 0) out[b] = ll - 4095.0f * logf(128.0f);
}

// ---------------------------------------------------------------------------
extern "C" void kernel_launch(void* const* d_in, const int* in_sizes, int n_in,
                              void* d_out, int out_size) {
    const float* inputs = nullptr;
    const float* A      = nullptr;
    const float* Bm     = nullptr;
    const float* Ivec   = nullptr;
    for (int i = 0; i < n_in; ++i) {
        switch (in_sizes[i]) {
            case NBATCH * T_LEN * E_DIM: inputs = (const float*)d_in[i]; break;
            case S_REAL * S_REAL:        A      = (const float*)d_in[i]; break;
            case S_REAL * E_DIM:         Bm     = (const float*)d_in[i]; break;
            case S_REAL:                 Ivec   = (const float*)d_in[i]; break;
            default: break;
        }
    }
    if (!inputs) inputs = (const float*)d_in[0];
    if (!A)      A      = (const float*)d_in[1];
    if (!Bm)     Bm     = (const float*)d_in[2];
    if (!Ivec)   Ivec   = (const float*)d_in[3];
    float* out = (float*)d_out;

    dim3 ggrid(SP / 64, (NBATCH * T_LEN) / 64);   // (5, 2048)
    prep_gemm_kernel<<<ggrid, 256>>>(inputs, Bm, A);

    scan_kernel<<<NBATCH, SCAN_THREADS>>>(Ivec, out);
    (void)out_size;
}

// round 14
// speedup vs baseline: 1.1970x; 1.0256x over previous
#include <cuda_runtime.h>
#include <cuda_bf16.h>
#include <stdint.h>

#define S_REAL   308
#define SP       320     // padded state count
#define E_DIM    126
#define T_LEN    4096
#define NBATCH   32
#define NIP      160     // SP/2 pair-words of alpha
#define SCAN_THREADS 512

// Scratch (device globals — no allocation in kernel_launch)
__device__ __nv_bfloat16 g_emis[(size_t)NBATCH * T_LEN * SP];   // 80 MB
// A pair-words for the 512-thread scan. Tile (ig, jj) owns i-pairs
// ip = ig*20 + ql*4 + s (ql=0..4, s=0..3) for columns j = jj + 64*c (c=0..4).
// uint4 (ql,c) lives at uint4 index ((ig*5+ql)*5 + c)*64 + jj. Prescaled x128.
__device__ uint32_t g_a[8 * 5 * 5 * 64 * 4];                     // 200 KB

__device__ __forceinline__ __nv_bfloat162 u32_bf2(uint32_t v) {
    return *reinterpret_cast<__nv_bfloat162*>(&v);
}
__device__ __forceinline__ uint32_t bf2_u32(__nv_bfloat162 v) {
    return *reinterpret_cast<uint32_t*>(&v);
}
// bf16x2 -> fp32 sum via ALU-pipe bit tricks (SHF/LOP), one FADD on fma pipe
__device__ __forceinline__ float bf2_sum(__nv_bfloat162 v) {
    uint32_t u = bf2_u32(v);
    return __uint_as_float(u << 16) + __uint_as_float(u & 0xffff0000u);
}

// ---------------------------------------------------------------------------
// Merged prep + emission GEMM. Blocks (bx==0, by<80) pack A*128 into g_a,
// then all blocks run the emission GEMM tile. 2 launches per call total.
// ---------------------------------------------------------------------------
__global__ void __launch_bounds__(256)
prep_gemm_kernel(const float* __restrict__ inp, const float* __restrict__ Bm,
                 const float* __restrict__ A) {
    const int tid = threadIdx.x;

    if (blockIdx.x == 0 && blockIdx.y < 80) {
        int gt = blockIdx.y * 256 + tid;
        for (int wi = gt; wi < 160 * SP; wi += 80 * 256) {
            int ip = wi / SP;
            int j  = wi - ip * SP;
            int i0 = 2 * ip, i1 = i0 + 1;
            float a0 = (i0 < S_REAL && j < S_REAL) ? A[i0 * S_REAL + j] * 128.f : 0.f;
            float a1 = (i1 < S_REAL && j < S_REAL) ? A[i1 * S_REAL + j] * 128.f : 0.f;
            uint32_t word = bf2_u32(__floats2bfloat162_rn(a0, a1));
            int ig = ip / 20, r = ip % 20, ql = r >> 2, s = r & 3;
            int c = j >> 6, jj = j & 63;
            g_a[((((ig * 5 + ql) * 5 + c) * 64) + jj) * 4 + s] = word;
        }
    }

    // ---------------- GEMM part (all blocks) ----------------
    __shared__ uint32_t sAp[64][16];
    __shared__ uint32_t sBp[16][64];

    const int tx = tid & 15;
    const int ty = tid >> 4;
    const int n0 = blockIdx.x * 64;
    const int m0 = blockIdx.y * 64;

    float acc[4][4];
#pragma unroll
    for (int u = 0; u < 4; ++u)
#pragma unroll
        for (int v = 0; v < 4; ++v) acc[u][v] = 0.f;

    const __nv_bfloat162 zero2 = __floats2bfloat162_rn(0.f, 0.f);

    for (int k0 = 0; k0 < 128; k0 += 32) {
#pragma unroll
        for (int r = 0; r < 4; ++r) {
            int lin = tid + r * 256;
            int mm = lin >> 4, kp = lin & 15;
            int k = k0 + 2 * kp;
            __nv_bfloat162 w = zero2;
            if (k < E_DIM) {
                float2 f = *reinterpret_cast<const float2*>(
                    &inp[(size_t)(m0 + mm) * E_DIM + k]);
                w = __floats2bfloat162_rn(f.x, f.y);
            }
            sAp[mm][kp] = bf2_u32(w);
        }
#pragma unroll
        for (int r = 0; r < 4; ++r) {
            int lin = tid + r * 256;
            int kp = lin >> 6, n = lin & 63;
            int k = k0 + 2 * kp;
            int nn = n0 + n;
            __nv_bfloat162 w = zero2;
            if (k < E_DIM && nn < S_REAL) {
                float2 f = *reinterpret_cast<const float2*>(
                    &Bm[(size_t)nn * E_DIM + k]);
                w = __floats2bfloat162_rn(f.x, f.y);
            }
            sBp[kp][n] = bf2_u32(w);
        }
        __syncthreads();

        __nv_bfloat162 acc2[4][4];
#pragma unroll
        for (int u = 0; u < 4; ++u)
#pragma unroll
            for (int v = 0; v < 4; ++v) acc2[u][v] = zero2;

#pragma unroll
        for (int kp = 0; kp < 16; ++kp) {
            uint4 bv = *reinterpret_cast<const uint4*>(&sBp[kp][tx * 4]);
            uint32_t a0 = sAp[ty * 4 + 0][kp];
            uint32_t a1 = sAp[ty * 4 + 1][kp];
            uint32_t a2 = sAp[ty * 4 + 2][kp];
            uint32_t a3 = sAp[ty * 4 + 3][kp];
            __nv_bfloat162 b0 = u32_bf2(bv.x), b1 = u32_bf2(bv.y);
            __nv_bfloat162 b2 = u32_bf2(bv.z), b3 = u32_bf2(bv.w);
            acc2[0][0] = __hfma2(u32_bf2(a0), b0, acc2[0][0]);
            acc2[0][1] = __hfma2(u32_bf2(a0), b1, acc2[0][1]);
            acc2[0][2] = __hfma2(u32_bf2(a0), b2, acc2[0][2]);
            acc2[0][3] = __hfma2(u32_bf2(a0), b3, acc2[0][3]);
            acc2[1][0] = __hfma2(u32_bf2(a1), b0, acc2[1][0]);
            acc2[1][1] = __hfma2(u32_bf2(a1), b1, acc2[1][1]);
            acc2[1][2] = __hfma2(u32_bf2(a1), b2, acc2[1][2]);
            acc2[1][3] = __hfma2(u32_bf2(a1), b3, acc2[1][3]);
            acc2[2][0] = __hfma2(u32_bf2(a2), b0, acc2[2][0]);
            acc2[2][1] = __hfma2(u32_bf2(a2), b1, acc2[2][1]);
            acc2[2][2] = __hfma2(u32_bf2(a2), b2, acc2[2][2]);
            acc2[2][3] = __hfma2(u32_bf2(a2), b3, acc2[2][3]);
            acc2[3][0] = __hfma2(u32_bf2(a3), b0, acc2[3][0]);
            acc2[3][1] = __hfma2(u32_bf2(a3), b1, acc2[3][1]);
            acc2[3][2] = __hfma2(u32_bf2(a3), b2, acc2[3][2]);
            acc2[3][3] = __hfma2(u32_bf2(a3), b3, acc2[3][3]);
        }
#pragma unroll
        for (int u = 0; u < 4; ++u)
#pragma unroll
            for (int v = 0; v < 4; ++v) {
                float2 p = __bfloat1622float2(acc2[u][v]);
                acc[u][v] += p.x + p.y;
            }
        __syncthreads();
    }
#pragma unroll
    for (int u = 0; u < 4; ++u) {
        int m = m0 + ty * 4 + u;
        size_t base = (size_t)m * SP + n0 + tx * 4;
#pragma unroll
        for (int v = 0; v < 4; v += 2) {
            __nv_bfloat162 p = __floats2bfloat162_rn(acc[u][v], acc[u][v + 1]);
            *reinterpret_cast<uint32_t*>(&g_emis[base + v]) = bf2_u32(p);
        }
    }
}

// ---------------------------------------------------------------------------
// Scan: one CTA per batch, 512 threads (16 warps). R13 skeleton: thread
// (ig = tid>>6, jj = tid&63) owns a 20-i-pair x 5-column A tile, fully
// register-resident (25 uint4 = 100 regs); warp-uniform alpha broadcasts;
// smem s_red 8-way reduce; 2 barriers/step; deferred renorm. Changes vs R13:
//  - pack shuffle ELIMINATED: each reducer stores its bf16 result as a
//    16-bit STS (same buffer layout for the uint4 readers)
//  - renorm partials computed AFTER the alpha store (overlaps STS drain)
//  - branch-free emission prefetch
// A prescaled by 128; ll -= 4095*log(128).
// ---------------------------------------------------------------------------
__global__ void __launch_bounds__(SCAN_THREADS, 1)
scan_kernel(const float* __restrict__ Ivec, float* __restrict__ out) {
    __shared__ uint32_t s_alpha[2][NIP];   // bf16 alpha pairs, double-buffered
    __shared__ float    s_w[10];
    __shared__ float    s_red[8][SP];      // per-i-group partials
    __shared__ float    s_inv;

    const int b    = blockIdx.x;
    const int tid  = threadIdx.x;
    const int ig   = tid >> 6;             // 0..7  (i-pair group of 20)
    const int jj   = tid & 63;             // 0..63
    const int wrp  = tid >> 5;
    const int lane = tid & 31;

    const __nv_bfloat16* erow = g_emis + (size_t)b * T_LEN * SP;
    const uint4* Aq = reinterpret_cast<const uint4*>(g_a);

    // whole A tile register-resident: rA[ql*5 + c], 25 uint4 = 100 regs
    uint4 rA[25];
#pragma unroll
    for (int ql = 0; ql < 5; ++ql)
#pragma unroll
        for (int c = 0; c < 5; ++c)
            rA[ql * 5 + c] = Aq[(((ig * 5 + ql) * 5 + c) * 64) + jj];

    // t = 0: alpha0 = I * e0 (unnormalized, NOT prescaled) into buffer 1
    if (tid < NIP) {
        int j0 = 2 * tid, j1 = j0 + 1;
        float e0 = __bfloat162float(erow[j0]);
        float e1 = __bfloat162float(erow[j1]);
        float w0 = (j0 < S_REAL) ? Ivec[j0] : 0.f;
        float w1 = (j1 < S_REAL) ? Ivec[j1] : 0.f;
        s_alpha[1][tid] = bf2_u32(__floats2bfloat162_rn(w0 * e0, w1 * e1));
    }
    if (tid == 0) s_inv = 1.0f;
    __syncthreads();

    float ll = 0.f;
    float e_cur = 0.f;
    if (tid < SP) e_cur = __bfloat162float(erow[(size_t)SP + tid]);

    const __nv_bfloat162 zero2 = __floats2bfloat162_rn(0.f, 0.f);

    for (int t = 1; t < T_LEN; ++t) {
        const int cur = t & 1;
        // branch-free prefetch of next step's emission (last step re-reads t)
        int tn = (t + 1 < T_LEN) ? (t + 1) : t;
        float e_next = 0.f;
        if (tid < SP) e_next = __bfloat162float(erow[(size_t)tn * SP + tid]);

        const uint4* al4 = reinterpret_cast<const uint4*>(s_alpha[cur]);

        __nv_bfloat162 a0 = zero2, a1 = zero2, a2 = zero2, a3 = zero2, a4 = zero2;

        // 5 broadcast alpha quads; accumulators interleaved (s-outer, c-inner)
#pragma unroll
        for (int ql = 0; ql < 5; ++ql) {
            uint4 av = al4[ig * 5 + ql];
            uint4 w0 = rA[ql * 5 + 0], w1 = rA[ql * 5 + 1], w2 = rA[ql * 5 + 2];
            uint4 w3 = rA[ql * 5 + 3], w4 = rA[ql * 5 + 4];
            __nv_bfloat162 x;
            x = u32_bf2(av.x);
            a0 = __hfma2(u32_bf2(w0.x), x, a0);
            a1 = __hfma2(u32_bf2(w1.x), x, a1);
            a2 = __hfma2(u32_bf2(w2.x), x, a2);
            a3 = __hfma2(u32_bf2(w3.x), x, a3);
            a4 = __hfma2(u32_bf2(w4.x), x, a4);
            x = u32_bf2(av.y);
            a0 = __hfma2(u32_bf2(w0.y), x, a0);
            a1 = __hfma2(u32_bf2(w1.y), x, a1);
            a2 = __hfma2(u32_bf2(w2.y), x, a2);
            a3 = __hfma2(u32_bf2(w3.y), x, a3);
            a4 = __hfma2(u32_bf2(w4.y), x, a4);
            x = u32_bf2(av.z);
            a0 = __hfma2(u32_bf2(w0.z), x, a0);
            a1 = __hfma2(u32_bf2(w1.z), x, a1);
            a2 = __hfma2(u32_bf2(w2.z), x, a2);
            a3 = __hfma2(u32_bf2(w3.z), x, a3);
            a4 = __hfma2(u32_bf2(w4.z), x, a4);
            x = u32_bf2(av.w);
            a0 = __hfma2(u32_bf2(w0.w), x, a0);
            a1 = __hfma2(u32_bf2(w1.w), x, a1);
            a2 = __hfma2(u32_bf2(w2.w), x, a2);
            a3 = __hfma2(u32_bf2(w3.w), x, a3);
            a4 = __hfma2(u32_bf2(w4.w), x, a4);
        }

        // collapse via ALU-pipe bit tricks, store per-i-group partials
        s_red[ig][jj      ] = bf2_sum(a0);
        s_red[ig][jj + 64 ] = bf2_sum(a1);
        s_red[ig][jj + 128] = bf2_sum(a2);
        s_red[ig][jj + 192] = bf2_sum(a3);
        s_red[ig][jj + 256] = bf2_sum(a4);
        __syncthreads();                         // BAR1

        float o = 0.f;
        if (tid < SP) {
            o = ((s_red[0][tid] + s_red[1][tid]) + (s_red[2][tid] + s_red[3][tid]))
              + ((s_red[4][tid] + s_red[5][tid]) + (s_red[6][tid] + s_red[7][tid]));
            o *= e_cur;
            if ((t & 15) == 0) o *= s_inv;       // deferred scale from t-1

            // direct 16-bit store of the new alpha (no pack shuffle);
            // halfword j of the pair buffer == alpha[j] for the uint4 readers
            reinterpret_cast<__nv_bfloat16*>(s_alpha[cur ^ 1])[tid] =
                __float2bfloat16(o);
        }

        if ((t & 15) == 15) {
            // z warp-partials AFTER the alpha store (overlaps STS drain);
            // warps 0..9 hold all 320 j's
            if (wrp < 10) {
                float s = o;
#pragma unroll
                for (int off = 16; off > 0; off >>= 1)
                    s += __shfl_xor_sync(0xffffffffu, s, off);
                if (lane == 0) s_w[wrp] = s;
            }
        }
        __syncthreads();                         // BAR2

        if ((t & 15) == 15 && tid == 0) {
            // overlapped with the next step's fma phase; readers consume
            // s_inv only after the next BAR1.
            float z = 0.f;
#pragma unroll
            for (int k = 0; k < 10; ++k) z += s_w[k];
            ll += logf(z);
            s_inv = 1.0f / z;
        }

        e_cur = e_next;
    }

    // each of the 4095 steps carried an extra factor 128 (folded into A);
    // last renorm lands exactly on t=4095, so ll is complete.
    if (tid == 0) out[b] = ll - 4095.0f * logf(128.0f);
}

// ---------------------------------------------------------------------------
extern "C" void kernel_launch(void* const* d_in, const int* in_sizes, int n_in,
                              void* d_out, int out_size) {
    const float* inputs = nullptr;
    const float* A      = nullptr;
    const float* Bm     = nullptr;
    const float* Ivec   = nullptr;
    for (int i = 0; i < n_in; ++i) {
        switch (in_sizes[i]) {
            case NBATCH * T_LEN * E_DIM: inputs = (const float*)d_in[i]; break;
            case S_REAL * S_REAL:        A      = (const float*)d_in[i]; break;
            case S_REAL * E_DIM:         Bm     = (const float*)d_in[i]; break;
            case S_REAL:                 Ivec   = (const float*)d_in[i]; break;
            default: break;
        }
    }
    if (!inputs) inputs = (const float*)d_in[0];
    if (!A)      A      = (const float*)d_in[1];
    if (!Bm)     Bm     = (const float*)d_in[2];
    if (!Ivec)   Ivec   = (const float*)d_in[3];
    float* out = (float*)d_out;

    dim3 ggrid(SP / 64, (NBATCH * T_LEN) / 64);   // (5, 2048)
    prep_gemm_kernel<<<ggrid, 256>>>(inputs, Bm, A);

    scan_kernel<<<NBATCH, SCAN_THREADS>>>(Ivec, out);
    (void)out_size;
}

// round 16
// speedup vs baseline: 1.2532x; 1.0470x over previous
#include <cuda_runtime.h>
#include <cuda_bf16.h>
#include <stdint.h>

#define S_REAL   308
#define SP       320     // padded state count
#define E_DIM    126
#define T_LEN    4096
#define NBATCH   32
#define NIP      160     // SP/2 pair-words of alpha
#define THREADS  512
#define NTILE    5       // n-tiles (64 cols) per 64-row block
#define KBLKS    64      // 64-row t-blocks per batch
#define NSCAN    32      // scan blocks (one per batch)

// Scratch (device globals — no allocation in kernel_launch)
__device__ __nv_bfloat16 g_emis[(size_t)NBATCH * T_LEN * SP];   // 80 MB
__device__ int           g_flags[NBATCH * KBLKS];                // 8 KB

__device__ __forceinline__ __nv_bfloat162 u32_bf2(uint32_t v) {
    return *reinterpret_cast<__nv_bfloat162*>(&v);
}
__device__ __forceinline__ uint32_t bf2_u32(__nv_bfloat162 v) {
    return *reinterpret_cast<uint32_t*>(&v);
}
// bf16x2 -> fp32 sum via ALU-pipe bit tricks (SHF/LOP), one FADD on fma pipe
__device__ __forceinline__ float bf2_sum(__nv_bfloat162 v) {
    uint32_t u = bf2_u32(v);
    return __uint_as_float(u << 16) + __uint_as_float(u & 0xffff0000u);
}
// spin until all 5 n-tiles of a 64-row block have released
__device__ __forceinline__ void wait_flag5(const int* p) {
    int v;
    do {
        asm volatile("ld.acquire.gpu.global.s32 %0, [%1];"
                     : "=r"(v) : "l"(p) : "memory");
    } while (v < NTILE);
}

// ---------------------------------------------------------------------------
__global__ void zero_flags_kernel() {
    int i = blockIdx.x * 256 + threadIdx.x;
    if (i < NBATCH * KBLKS) g_flags[i] = 0;
}

// ---------------------------------------------------------------------------
// Fused kernel. Blocks 0..31: per-batch scan (persistent, wave-1 resident).
// Blocks 32..: emission GEMM tiles (64m x 64n, k=128), t-block-major order so
// every batch's early rows are produced first. Producer->consumer handoff via
// g_flags (release-add by producers, acquire-poll by the scan every 64 steps).
// ALL shared arrays accessed via uint4 are explicitly 16B-aligned (R15 fix).
// ---------------------------------------------------------------------------
__global__ void __launch_bounds__(THREADS, 1)
fused_kernel(const float* __restrict__ inp, const float* __restrict__ Bm,
             const float* __restrict__ A,   const float* __restrict__ Ivec,
             float* __restrict__ out) {
    __shared__ __align__(16) uint32_t s_alpha[2][NIP];  // bf16 alpha pairs
    __shared__ __align__(16) float    s_red[8][SP];     // per-i-group partials
    __shared__ __align__(16) uint32_t sAp[64][16];      // gemm: inputs tile
    __shared__ __align__(16) uint32_t sBp[16][64];      // gemm: B tile
    __shared__ float s_w[10];
    __shared__ float s_inv;

    const int tid = threadIdx.x;
    const __nv_bfloat162 zero2 = __floats2bfloat162_rn(0.f, 0.f);

    if (blockIdx.x >= NSCAN) {
        // ==================== GEMM tile ====================
        const int gbid = blockIdx.x - NSCAN;
        const int n0   = (gbid % NTILE) * 64;
        const int bt   = gbid / NTILE;      // 0..2047
        const int bb   = bt & 31;           // batch (inner)
        const int kblk = bt >> 5;           // t-block (outer)
        const int m0   = bb * T_LEN + kblk * 64;

        const int tx = tid & 15;
        const int ty = tid >> 4;            // 0..31

        float acc[2][4];
#pragma unroll
        for (int u = 0; u < 2; ++u)
#pragma unroll
            for (int v = 0; v < 4; ++v) acc[u][v] = 0.f;

        for (int k0 = 0; k0 < 128; k0 += 32) {
#pragma unroll
            for (int r = 0; r < 2; ++r) {
                int lin = tid + r * THREADS;
                int mm = lin >> 4, kp = lin & 15;
                int k = k0 + 2 * kp;
                __nv_bfloat162 w = zero2;
                if (k < E_DIM) {
                    float2 f = *reinterpret_cast<const float2*>(
                        &inp[(size_t)(m0 + mm) * E_DIM + k]);
                    w = __floats2bfloat162_rn(f.x, f.y);
                }
                sAp[mm][kp] = bf2_u32(w);
            }
#pragma unroll
            for (int r = 0; r < 2; ++r) {
                int lin = tid + r * THREADS;
                int kp = lin >> 6, n = lin & 63;
                int k = k0 + 2 * kp;
                int nn = n0 + n;
                __nv_bfloat162 w = zero2;
                if (k < E_DIM && nn < S_REAL) {
                    float2 f = *reinterpret_cast<const float2*>(
                        &Bm[(size_t)nn * E_DIM + k]);
                    w = __floats2bfloat162_rn(f.x, f.y);
                }
                sBp[kp][n] = bf2_u32(w);
            }
            __syncthreads();

            __nv_bfloat162 acc2[2][4];
#pragma unroll
            for (int u = 0; u < 2; ++u)
#pragma unroll
                for (int v = 0; v < 4; ++v) acc2[u][v] = zero2;

#pragma unroll
            for (int kp = 0; kp < 16; ++kp) {
                uint4 bv = *reinterpret_cast<const uint4*>(&sBp[kp][tx * 4]);
                uint32_t a0 = sAp[ty * 2 + 0][kp];
                uint32_t a1 = sAp[ty * 2 + 1][kp];
                __nv_bfloat162 b0 = u32_bf2(bv.x), b1 = u32_bf2(bv.y);
                __nv_bfloat162 b2 = u32_bf2(bv.z), b3 = u32_bf2(bv.w);
                acc2[0][0] = __hfma2(u32_bf2(a0), b0, acc2[0][0]);
                acc2[0][1] = __hfma2(u32_bf2(a0), b1, acc2[0][1]);
                acc2[0][2] = __hfma2(u32_bf2(a0), b2, acc2[0][2]);
                acc2[0][3] = __hfma2(u32_bf2(a0), b3, acc2[0][3]);
                acc2[1][0] = __hfma2(u32_bf2(a1), b0, acc2[1][0]);
                acc2[1][1] = __hfma2(u32_bf2(a1), b1, acc2[1][1]);
                acc2[1][2] = __hfma2(u32_bf2(a1), b2, acc2[1][2]);
                acc2[1][3] = __hfma2(u32_bf2(a1), b3, acc2[1][3]);
            }
#pragma unroll
            for (int u = 0; u < 2; ++u)
#pragma unroll
                for (int v = 0; v < 4; ++v) {
                    float2 p = __bfloat1622float2(acc2[u][v]);
                    acc[u][v] += p.x + p.y;
                }
            __syncthreads();
        }
#pragma unroll
        for (int u = 0; u < 2; ++u) {
            int m = m0 + ty * 2 + u;
            size_t base = (size_t)m * SP + n0 + tx * 4;
#pragma unroll
            for (int v = 0; v < 4; v += 2) {
                __nv_bfloat162 p = __floats2bfloat162_rn(acc[u][v], acc[u][v + 1]);
                *reinterpret_cast<uint32_t*>(&g_emis[base + v]) = bf2_u32(p);
            }
        }
        // release this tile's contribution to the (batch, t-block) flag
        __threadfence();
        __syncthreads();
        if (tid == 0)
            asm volatile("red.release.gpu.global.add.s32 [%0], 1;"
                         :: "l"(&g_flags[bb * KBLKS + kblk]) : "memory");
        return;
    }

    // ==================== scan (R14 inner loop) ====================
    const int b    = blockIdx.x;
    const int ig   = tid >> 6;             // 0..7  (i-pair group of 20)
    const int jj   = tid & 63;             // 0..63
    const int wrp  = tid >> 5;
    const int lane = tid & 31;

    const __nv_bfloat16* erow = g_emis + (size_t)b * T_LEN * SP;
    const int* fl = &g_flags[b * KBLKS];

    // gather the register-resident A tile directly from fp32 A (prescale x128)
    uint4 rA[25];
#pragma unroll
    for (int ql = 0; ql < 5; ++ql)
#pragma unroll
        for (int c = 0; c < 5; ++c) {
            int j = jj + 64 * c;
            uint32_t w[4];
#pragma unroll
            for (int s = 0; s < 4; ++s) {
                int ip = ig * 20 + ql * 4 + s;
                int i0 = 2 * ip, i1 = i0 + 1;
                float a0 = (i0 < S_REAL && j < S_REAL) ? A[i0 * S_REAL + j] * 128.f : 0.f;
                float a1 = (i1 < S_REAL && j < S_REAL) ? A[i1 * S_REAL + j] * 128.f : 0.f;
                w[s] = bf2_u32(__floats2bfloat162_rn(a0, a1));
            }
            rA[ql * 5 + c] = make_uint4(w[0], w[1], w[2], w[3]);
        }

    // rows 0..63 must be produced before init reads rows 0 and 1
    wait_flag5(fl);

    // t = 0: alpha0 = I * e0 (unnormalized, NOT prescaled) into buffer 1
    if (tid < NIP) {
        int j0 = 2 * tid, j1 = j0 + 1;
        float e0 = __bfloat162float(erow[j0]);
        float e1 = __bfloat162float(erow[j1]);
        float w0 = (j0 < S_REAL) ? Ivec[j0] : 0.f;
        float w1 = (j1 < S_REAL) ? Ivec[j1] : 0.f;
        s_alpha[1][tid] = bf2_u32(__floats2bfloat162_rn(w0 * e0, w1 * e1));
    }
    if (tid == 0) s_inv = 1.0f;
    __syncthreads();

    float ll = 0.f;
    float e_cur = 0.f;
    if (tid < SP) e_cur = __bfloat162float(erow[(size_t)SP + tid]);

    for (int t = 1; t < T_LEN; ++t) {
        const int cur = t & 1;

        // gate before prefetching into the next 64-row block
        if ((t & 63) == 63 && t + 1 < T_LEN)
            wait_flag5(fl + ((t + 1) >> 6));

        // branch-free prefetch of next step's emission (last step re-reads t)
        int tn = (t + 1 < T_LEN) ? (t + 1) : t;
        float e_next = 0.f;
        if (tid < SP) e_next = __bfloat162float(erow[(size_t)tn * SP + tid]);

        const uint4* al4 = reinterpret_cast<const uint4*>(s_alpha[cur]);

        __nv_bfloat162 a0 = zero2, a1 = zero2, a2 = zero2, a3 = zero2, a4 = zero2;

        // 5 broadcast alpha quads; accumulators interleaved (s-outer, c-inner)
#pragma unroll
        for (int ql = 0; ql < 5; ++ql) {
            uint4 av = al4[ig * 5 + ql];
            uint4 w0 = rA[ql * 5 + 0], w1 = rA[ql * 5 + 1], w2 = rA[ql * 5 + 2];
            uint4 w3 = rA[ql * 5 + 3], w4 = rA[ql * 5 + 4];
            __nv_bfloat162 x;
            x = u32_bf2(av.x);
            a0 = __hfma2(u32_bf2(w0.x), x, a0);
            a1 = __hfma2(u32_bf2(w1.x), x, a1);
            a2 = __hfma2(u32_bf2(w2.x), x, a2);
            a3 = __hfma2(u32_bf2(w3.x), x, a3);
            a4 = __hfma2(u32_bf2(w4.x), x, a4);
            x = u32_bf2(av.y);
            a0 = __hfma2(u32_bf2(w0.y), x, a0);
            a1 = __hfma2(u32_bf2(w1.y), x, a1);
            a2 = __hfma2(u32_bf2(w2.y), x, a2);
            a3 = __hfma2(u32_bf2(w3.y), x, a3);
            a4 = __hfma2(u32_bf2(w4.y), x, a4);
            x = u32_bf2(av.z);
            a0 = __hfma2(u32_bf2(w0.z), x, a0);
            a1 = __hfma2(u32_bf2(w1.z), x, a1);
            a2 = __hfma2(u32_bf2(w2.z), x, a2);
            a3 = __hfma2(u32_bf2(w3.z), x, a3);
            a4 = __hfma2(u32_bf2(w4.z), x, a4);
            x = u32_bf2(av.w);
            a0 = __hfma2(u32_bf2(w0.w), x, a0);
            a1 = __hfma2(u32_bf2(w1.w), x, a1);
            a2 = __hfma2(u32_bf2(w2.w), x, a2);
            a3 = __hfma2(u32_bf2(w3.w), x, a3);
            a4 = __hfma2(u32_bf2(w4.w), x, a4);
        }

        // collapse via ALU-pipe bit tricks, store per-i-group partials
        s_red[ig][jj      ] = bf2_sum(a0);
        s_red[ig][jj + 64 ] = bf2_sum(a1);
        s_red[ig][jj + 128] = bf2_sum(a2);
        s_red[ig][jj + 192] = bf2_sum(a3);
        s_red[ig][jj + 256] = bf2_sum(a4);
        __syncthreads();                         // BAR1

        float o = 0.f;
        if (tid < SP) {
            o = ((s_red[0][tid] + s_red[1][tid]) + (s_red[2][tid] + s_red[3][tid]))
              + ((s_red[4][tid] + s_red[5][tid]) + (s_red[6][tid] + s_red[7][tid]));
            o *= e_cur;
            if ((t & 15) == 0) o *= s_inv;       // deferred scale from t-1

            // direct 16-bit store of the new alpha (no pack shuffle)
            reinterpret_cast<__nv_bfloat16*>(s_alpha[cur ^ 1])[tid] =
                __float2bfloat16(o);
        }

        if ((t & 15) == 15) {
            // z warp-partials AFTER the alpha store (overlaps STS drain)
            if (wrp < 10) {
                float s = o;
#pragma unroll
                for (int off = 16; off > 0; off >>= 1)
                    s += __shfl_xor_sync(0xffffffffu, s, off);
                if (lane == 0) s_w[wrp] = s;
            }
        }
        __syncthreads();                         // BAR2

        if ((t & 15) == 15 && tid == 0) {
            // overlapped with the next step's fma phase
            float z = 0.f;
#pragma unroll
            for (int k = 0; k < 10; ++k) z += s_w[k];
            ll += logf(z);
            s_inv = 1.0f / z;
        }

        e_cur = e_next;
    }

    // each of the 4095 steps carried an extra factor 128 (folded into A);
    // last renorm lands exactly on t=4095, so ll is complete.
    if (tid == 0) out[b] = ll - 4095.0f * logf(128.0f);
}

// ---------------------------------------------------------------------------
extern "C" void kernel_launch(void* const* d_in, const int* in_sizes, int n_in,
                              void* d_out, int out_size) {
    const float* inputs = nullptr;
    const float* A      = nullptr;
    const float* Bm     = nullptr;
    const float* Ivec   = nullptr;
    for (int i = 0; i < n_in; ++i) {
        switch (in_sizes[i]) {
            case NBATCH * T_LEN * E_DIM: inputs = (const float*)d_in[i]; break;
            case S_REAL * S_REAL:        A      = (const float*)d_in[i]; break;
            case S_REAL * E_DIM:         Bm     = (const float*)d_in[i]; break;
            case S_REAL:                 Ivec   = (const float*)d_in[i]; break;
            default: break;
        }
    }
    if (!inputs) inputs = (const float*)d_in[0];
    if (!A)      A      = (const float*)d_in[1];
    if (!Bm)     Bm     = (const float*)d_in[2];
    if (!Ivec)   Ivec   = (const float*)d_in[3];
    float* out = (float*)d_out;

    zero_flags_kernel<<<(NBATCH * KBLKS + 255) / 256, 256>>>();

    const int n_gemm = NTILE * (NBATCH * T_LEN / 64);   // 10240
    fused_kernel<<<NSCAN + n_gemm, THREADS>>>(inputs, Bm, A, Ivec, out);
    (void)out_size;
}

// round 17
// speedup vs baseline: 1.3055x; 1.0417x over previous
#include <cuda_runtime.h>
#include <cuda_bf16.h>
#include <stdint.h>

#define S_REAL   308
#define SP       320     // padded state count
#define E_DIM    126
#define T_LEN    4096
#define NBATCH   32
#define NIP      160     // SP/2 pair-words of alpha
#define THREADS  512
#define NTILE    5       // n-tiles (64 cols) per 64-row block
#define KBLKS    64      // 64-row t-blocks per batch
#define NSCAN    32      // scan blocks (one per batch)

// Scratch (device globals — no allocation in kernel_launch)
__device__ __nv_bfloat16 g_emis[(size_t)NBATCH * T_LEN * SP];   // 80 MB
__device__ int           g_flags[NBATCH * KBLKS];                // 8 KB

__device__ __forceinline__ __nv_bfloat162 u32_bf2(uint32_t v) {
    return *reinterpret_cast<__nv_bfloat162*>(&v);
}
__device__ __forceinline__ uint32_t bf2_u32(__nv_bfloat162 v) {
    return *reinterpret_cast<uint32_t*>(&v);
}
// bf16x2 -> fp32 sum via ALU-pipe bit tricks (SHF/LOP), one FADD on fma pipe
__device__ __forceinline__ float bf2_sum(__nv_bfloat162 v) {
    uint32_t u = bf2_u32(v);
    return __uint_as_float(u << 16) + __uint_as_float(u & 0xffff0000u);
}
// spin until all 5 n-tiles of a 64-row block have released
__device__ __forceinline__ void wait_flag5(const int* p) {
    int v;
    do {
        asm volatile("ld.acquire.gpu.global.s32 %0, [%1];"
                     : "=r"(v) : "l"(p) : "memory");
    } while (v < NTILE);
}

// ---------------------------------------------------------------------------
__global__ void zero_flags_kernel() {
    int i = blockIdx.x * 256 + threadIdx.x;
    if (i < NBATCH * KBLKS) g_flags[i] = 0;
}

// ---------------------------------------------------------------------------
// Fused kernel. Blocks 0..31: per-batch scan (persistent, wave-1 resident).
// Blocks 32..: emission GEMM tiles (64m x 64n, k=128), t-block-major order so
// every batch's early rows are produced first. Producer->consumer handoff via
// g_flags (release-add by producers, acquire-poll by the scan every 64 steps).
// ---------------------------------------------------------------------------
__global__ void __launch_bounds__(THREADS, 1)
fused_kernel(const float* __restrict__ inp, const float* __restrict__ Bm,
             const float* __restrict__ A,   const float* __restrict__ Ivec,
             float* __restrict__ out) {
    __shared__ __align__(16) uint32_t s_alpha[2][NIP];  // bf16 alpha pairs
    __shared__ __align__(16) uint32_t s_red[8][SP];     // bf16x2 partials
    __shared__ __align__(16) uint32_t sAp[64][16];      // gemm: inputs tile
    __shared__ __align__(16) uint32_t sBp[16][64];      // gemm: B tile
    __shared__ float s_w[10];
    __shared__ float s_inv;

    const int tid = threadIdx.x;
    const __nv_bfloat162 zero2 = __floats2bfloat162_rn(0.f, 0.f);

    if (blockIdx.x >= NSCAN) {
        // ==================== GEMM tile ====================
        const int gbid = blockIdx.x - NSCAN;
        const int n0   = (gbid % NTILE) * 64;
        const int bt   = gbid / NTILE;      // 0..2047
        const int bb   = bt & 31;           // batch (inner)
        const int kblk = bt >> 5;           // t-block (outer)
        const int m0   = bb * T_LEN + kblk * 64;

        const int tx = tid & 15;
        const int ty = tid >> 4;            // 0..31

        float acc[2][4];
#pragma unroll
        for (int u = 0; u < 2; ++u)
#pragma unroll
            for (int v = 0; v < 4; ++v) acc[u][v] = 0.f;

        for (int k0 = 0; k0 < 128; k0 += 32) {
#pragma unroll
            for (int r = 0; r < 2; ++r) {
                int lin = tid + r * THREADS;
                int mm = lin >> 4, kp = lin & 15;
                int k = k0 + 2 * kp;
                __nv_bfloat162 w = zero2;
                if (k < E_DIM) {
                    float2 f = *reinterpret_cast<const float2*>(
                        &inp[(size_t)(m0 + mm) * E_DIM + k]);
                    w = __floats2bfloat162_rn(f.x, f.y);
                }
                sAp[mm][kp] = bf2_u32(w);
            }
#pragma unroll
            for (int r = 0; r < 2; ++r) {
                int lin = tid + r * THREADS;
                int kp = lin >> 6, n = lin & 63;
                int k = k0 + 2 * kp;
                int nn = n0 + n;
                __nv_bfloat162 w = zero2;
                if (k < E_DIM && nn < S_REAL) {
                    float2 f = *reinterpret_cast<const float2*>(
                        &Bm[(size_t)nn * E_DIM + k]);
                    w = __floats2bfloat162_rn(f.x, f.y);
                }
                sBp[kp][n] = bf2_u32(w);
            }
            __syncthreads();

            __nv_bfloat162 acc2[2][4];
#pragma unroll
            for (int u = 0; u < 2; ++u)
#pragma unroll
                for (int v = 0; v < 4; ++v) acc2[u][v] = zero2;

#pragma unroll
            for (int kp = 0; kp < 16; ++kp) {
                uint4 bv = *reinterpret_cast<const uint4*>(&sBp[kp][tx * 4]);
                uint32_t a0 = sAp[ty * 2 + 0][kp];
                uint32_t a1 = sAp[ty * 2 + 1][kp];
                __nv_bfloat162 b0 = u32_bf2(bv.x), b1 = u32_bf2(bv.y);
                __nv_bfloat162 b2 = u32_bf2(bv.z), b3 = u32_bf2(bv.w);
                acc2[0][0] = __hfma2(u32_bf2(a0), b0, acc2[0][0]);
                acc2[0][1] = __hfma2(u32_bf2(a0), b1, acc2[0][1]);
                acc2[0][2] = __hfma2(u32_bf2(a0), b2, acc2[0][2]);
                acc2[0][3] = __hfma2(u32_bf2(a0), b3, acc2[0][3]);
                acc2[1][0] = __hfma2(u32_bf2(a1), b0, acc2[1][0]);
                acc2[1][1] = __hfma2(u32_bf2(a1), b1, acc2[1][1]);
                acc2[1][2] = __hfma2(u32_bf2(a1), b2, acc2[1][2]);
                acc2[1][3] = __hfma2(u32_bf2(a1), b3, acc2[1][3]);
            }
#pragma unroll
            for (int u = 0; u < 2; ++u)
#pragma unroll
                for (int v = 0; v < 4; ++v) {
                    float2 p = __bfloat1622float2(acc2[u][v]);
                    acc[u][v] += p.x + p.y;
                }
            __syncthreads();
        }
#pragma unroll
        for (int u = 0; u < 2; ++u) {
            int m = m0 + ty * 2 + u;
            size_t base = (size_t)m * SP + n0 + tx * 4;
#pragma unroll
            for (int v = 0; v < 4; v += 2) {
                __nv_bfloat162 p = __floats2bfloat162_rn(acc[u][v], acc[u][v + 1]);
                *reinterpret_cast<uint32_t*>(&g_emis[base + v]) = bf2_u32(p);
            }
        }
        // release this tile's contribution to the (batch, t-block) flag
        __threadfence();
        __syncthreads();
        if (tid == 0)
            asm volatile("red.release.gpu.global.add.s32 [%0], 1;"
                         :: "l"(&g_flags[bb * KBLKS + kblk]) : "memory");
        return;
    }

    // ==================== scan ====================
    const int b    = blockIdx.x;
    const int ig   = tid >> 6;             // 0..7  (i-pair group of 20)
    const int jj   = tid & 63;             // 0..63
    const int wrp  = tid >> 5;
    const int lane = tid & 31;

    const __nv_bfloat16* erow = g_emis + (size_t)b * T_LEN * SP;
    const int* fl = &g_flags[b * KBLKS];

    // gather the register-resident A tile directly from fp32 A (prescale x128)
    uint4 rA[25];
#pragma unroll
    for (int ql = 0; ql < 5; ++ql)
#pragma unroll
        for (int c = 0; c < 5; ++c) {
            int j = jj + 64 * c;
            uint32_t w[4];
#pragma unroll
            for (int s = 0; s < 4; ++s) {
                int ip = ig * 20 + ql * 4 + s;
                int i0 = 2 * ip, i1 = i0 + 1;
                float a0 = (i0 < S_REAL && j < S_REAL) ? A[i0 * S_REAL + j] * 128.f : 0.f;
                float a1 = (i1 < S_REAL && j < S_REAL) ? A[i1 * S_REAL + j] * 128.f : 0.f;
                w[s] = bf2_u32(__floats2bfloat162_rn(a0, a1));
            }
            rA[ql * 5 + c] = make_uint4(w[0], w[1], w[2], w[3]);
        }

    // rows 0..63 must be produced before init reads rows 0 and 1
    wait_flag5(fl);

    // t = 0: alpha0 = I * e0 (unnormalized, NOT prescaled) into buffer 1
    if (tid < NIP) {
        int j0 = 2 * tid, j1 = j0 + 1;
        float e0 = __bfloat162float(erow[j0]);
        float e1 = __bfloat162float(erow[j1]);
        float w0 = (j0 < S_REAL) ? Ivec[j0] : 0.f;
        float w1 = (j1 < S_REAL) ? Ivec[j1] : 0.f;
        s_alpha[1][tid] = bf2_u32(__floats2bfloat162_rn(w0 * e0, w1 * e1));
    }
    if (tid == 0) s_inv = 1.0f;
    __syncthreads();

    float ll = 0.f;
    // incremental emission pointer (strength-reduced)
    const __nv_bfloat16* ep = erow + (size_t)SP + tid;   // row t=1
    float e_cur = 0.f;
    if (tid < SP) e_cur = __bfloat162float(*ep);

    for (int t = 1; t < T_LEN; ++t) {
        const int cur = t & 1;

        // gate before prefetching into the next 64-row block
        if ((t & 63) == 63 && t + 1 < T_LEN)
            wait_flag5(fl + ((t + 1) >> 6));

        // prefetch next step's emission (clamped at the final step)
        if (t + 1 < T_LEN) ep += SP;
        float e_next = 0.f;
        if (tid < SP) e_next = __bfloat162float(*ep);

        const uint4* al4 = reinterpret_cast<const uint4*>(s_alpha[cur]);

        __nv_bfloat162 a0 = zero2, a1 = zero2, a2 = zero2, a3 = zero2, a4 = zero2;

        // 5 broadcast alpha quads; accumulators interleaved (s-outer, c-inner)
#pragma unroll
        for (int ql = 0; ql < 5; ++ql) {
            uint4 av = al4[ig * 5 + ql];
            uint4 w0 = rA[ql * 5 + 0], w1 = rA[ql * 5 + 1], w2 = rA[ql * 5 + 2];
            uint4 w3 = rA[ql * 5 + 3], w4 = rA[ql * 5 + 4];
            __nv_bfloat162 x;
            x = u32_bf2(av.x);
            a0 = __hfma2(u32_bf2(w0.x), x, a0);
            a1 = __hfma2(u32_bf2(w1.x), x, a1);
            a2 = __hfma2(u32_bf2(w2.x), x, a2);
            a3 = __hfma2(u32_bf2(w3.x), x, a3);
            a4 = __hfma2(u32_bf2(w4.x), x, a4);
            x = u32_bf2(av.y);
            a0 = __hfma2(u32_bf2(w0.y), x, a0);
            a1 = __hfma2(u32_bf2(w1.y), x, a1);
            a2 = __hfma2(u32_bf2(w2.y), x, a2);
            a3 = __hfma2(u32_bf2(w3.y), x, a3);
            a4 = __hfma2(u32_bf2(w4.y), x, a4);
            x = u32_bf2(av.z);
            a0 = __hfma2(u32_bf2(w0.z), x, a0);
            a1 = __hfma2(u32_bf2(w1.z), x, a1);
            a2 = __hfma2(u32_bf2(w2.z), x, a2);
            a3 = __hfma2(u32_bf2(w3.z), x, a3);
            a4 = __hfma2(u32_bf2(w4.z), x, a4);
            x = u32_bf2(av.w);
            a0 = __hfma2(u32_bf2(w0.w), x, a0);
            a1 = __hfma2(u32_bf2(w1.w), x, a1);
            a2 = __hfma2(u32_bf2(w2.w), x, a2);
            a3 = __hfma2(u32_bf2(w3.w), x, a3);
            a4 = __hfma2(u32_bf2(w4.w), x, a4);
        }

        // store raw bf16x2 partials (no collapse — saves 5 FADD + 10 ALU/thread)
        s_red[ig][jj      ] = bf2_u32(a0);
        s_red[ig][jj + 64 ] = bf2_u32(a1);
        s_red[ig][jj + 128] = bf2_u32(a2);
        s_red[ig][jj + 192] = bf2_u32(a3);
        s_red[ig][jj + 256] = bf2_u32(a4);
        __syncthreads();                         // BAR1

        float o = 0.f;
        if (tid < SP) {
            // 8-way i-group reduce in bf16x2 (HADD2 tree), one final collapse
            __nv_bfloat162 h =
                __hadd2(__hadd2(__hadd2(u32_bf2(s_red[0][tid]), u32_bf2(s_red[1][tid])),
                                __hadd2(u32_bf2(s_red[2][tid]), u32_bf2(s_red[3][tid]))),
                        __hadd2(__hadd2(u32_bf2(s_red[4][tid]), u32_bf2(s_red[5][tid])),
                                __hadd2(u32_bf2(s_red[6][tid]), u32_bf2(s_red[7][tid]))));
            o = bf2_sum(h) * e_cur;
            if ((t & 15) == 0) o *= s_inv;       // deferred scale from t-1

            // direct 16-bit store of the new alpha (no pack shuffle)
            reinterpret_cast<__nv_bfloat16*>(s_alpha[cur ^ 1])[tid] =
                __float2bfloat16(o);
        }

        if ((t & 15) == 15) {
            // z warp-partials AFTER the alpha store (overlaps STS drain)
            if (wrp < 10) {
                float s = o;
#pragma unroll
                for (int off = 16; off > 0; off >>= 1)
                    s += __shfl_xor_sync(0xffffffffu, s, off);
                if (lane == 0) s_w[wrp] = s;
            }
        }
        __syncthreads();                         // BAR2

        if ((t & 15) == 15 && tid == 0) {
            // overlapped with the next step's fma phase
            float z = 0.f;
#pragma unroll
            for (int k = 0; k < 10; ++k) z += s_w[k];
            ll += logf(z);
            s_inv = 1.0f / z;
        }

        e_cur = e_next;
    }

    // each of the 4095 steps carried an extra factor 128 (folded into A);
    // last renorm lands exactly on t=4095, so ll is complete.
    if (tid == 0) out[b] = ll - 4095.0f * logf(128.0f);
}

// ---------------------------------------------------------------------------
extern "C" void kernel_launch(void* const* d_in, const int* in_sizes, int n_in,
                              void* d_out, int out_size) {
    const float* inputs = nullptr;
    const float* A      = nullptr;
    const float* Bm     = nullptr;
    const float* Ivec   = nullptr;
    for (int i = 0; i < n_in; ++i) {
        switch (in_sizes[i]) {
            case NBATCH * T_LEN * E_DIM: inputs = (const float*)d_in[i]; break;
            case S_REAL * S_REAL:        A      = (const float*)d_in[i]; break;
            case S_REAL * E_DIM:         Bm     = (const float*)d_in[i]; break;
            case S_REAL:                 Ivec   = (const float*)d_in[i]; break;
            default: break;
        }
    }
    if (!inputs) inputs = (const float*)d_in[0];
    if (!A)      A      = (const float*)d_in[1];
    if (!Bm)     Bm     = (const float*)d_in[2];
    if (!Ivec)   Ivec   = (const float*)d_in[3];
    float* out = (float*)d_out;

    zero_flags_kernel<<<(NBATCH * KBLKS + 255) / 256, 256>>>();

    const int n_gemm = NTILE * (NBATCH * T_LEN / 64);   // 10240
    fused_kernel<<<NSCAN + n_gemm, THREADS>>>(inputs, Bm, A, Ivec, out);
    (void)out_size;
}